// round 10
// baseline (speedup 1.0000x reference)
#include <cuda_runtime.h>
#include <cstdint>

#define BATCH   65536
#define LATENT  128
#define HID     256
#define GATES   1024
#define SEQN    50
#define NUCV    4
#define VOCAB   5
#define SOS_TOK 4

#define TB       32            // rows per CTA
#define CH       16            // rows per accumulation sweep
#define NTHREADS 256
#define PAD      34            // hT row padding (floats, even for float2)

// SMEM layout (float offsets)
#define OFF_HA    0
#define OFF_HB    8704         // 256*PAD
#define OFF_E     17408
#define OFF_WOUT  22528
#define OFF_ZS    23552
#define OFF_BOUT  27648
#define OFF_LOGIT 27652
#define OFF_TOK   27780
#define SMEM_FLOATS 27812
#define SMEM_BYTES  (SMEM_FLOATS * 4)

struct StepKeys { unsigned int k0[SEQN]; unsigned int k1[SEQN]; };

__device__ float g_E[VOCAB * GATES];   // precomputed emb[v] @ W_ih (no biases)

// ---------------- Threefry-2x32 (matches jax/_src/prng.py) ----------------
__host__ __device__ __forceinline__ unsigned int rotl32(unsigned int x, int d) {
    return (x << d) | (x >> (32 - d));
}

__host__ __device__ __forceinline__ void tf2x32(unsigned int k0, unsigned int k1,
                                                unsigned int x0, unsigned int x1,
                                                unsigned int& o0, unsigned int& o1)
{
    unsigned int k2 = k0 ^ k1 ^ 0x1BD11BDAu;
    x0 += k0; x1 += k1;
    x0 += x1; x1 = rotl32(x1, 13); x1 ^= x0;
    x0 += x1; x1 = rotl32(x1, 15); x1 ^= x0;
    x0 += x1; x1 = rotl32(x1, 26); x1 ^= x0;
    x0 += x1; x1 = rotl32(x1, 6);  x1 ^= x0;
    x0 += k1; x1 += k2 + 1u;
    x0 += x1; x1 = rotl32(x1, 17); x1 ^= x0;
    x0 += x1; x1 = rotl32(x1, 29); x1 ^= x0;
    x0 += x1; x1 = rotl32(x1, 16); x1 ^= x0;
    x0 += x1; x1 = rotl32(x1, 24); x1 ^= x0;
    x0 += k2; x1 += k0 + 2u;
    x0 += x1; x1 = rotl32(x1, 13); x1 ^= x0;
    x0 += x1; x1 = rotl32(x1, 15); x1 ^= x0;
    x0 += x1; x1 = rotl32(x1, 26); x1 ^= x0;
    x0 += x1; x1 = rotl32(x1, 6);  x1 ^= x0;
    x0 += k0; x1 += k1 + 3u;
    x0 += x1; x1 = rotl32(x1, 17); x1 ^= x0;
    x0 += x1; x1 = rotl32(x1, 29); x1 ^= x0;
    x0 += x1; x1 = rotl32(x1, 16); x1 ^= x0;
    x0 += x1; x1 = rotl32(x1, 24); x1 ^= x0;
    x0 += k1; x1 += k2 + 4u;
    x0 += x1; x1 = rotl32(x1, 13); x1 ^= x0;
    x0 += x1; x1 = rotl32(x1, 15); x1 ^= x0;
    x0 += x1; x1 = rotl32(x1, 26); x1 ^= x0;
    x0 += x1; x1 = rotl32(x1, 6);  x1 ^= x0;
    x0 += k2; x1 += k0 + 5u;
    o0 = x0; o1 = x1;
}

// ---------------- XLA-exact activations ----------------
// XLA elemental tanh f32: clamp to +-7.90531110763549805, 7/6-degree rational,
// passthrough for |x| < 0.0004. Separate mul/add (no contraction), matching XLA.
__device__ __forceinline__ float xla_tanh(float x) {
    float ax = fabsf(x);
    float xc = fminf(fmaxf(x, -7.90531110763549805f), 7.90531110763549805f);
    float x2 = __fmul_rn(xc, xc);
    float p = -2.76076847742355e-16f;
    p = __fadd_rn(__fmul_rn(p, x2), 2.00018790482477e-13f);
    p = __fadd_rn(__fmul_rn(p, x2), -8.60467152213735e-11f);
    p = __fadd_rn(__fmul_rn(p, x2), 5.12229709037114e-08f);
    p = __fadd_rn(__fmul_rn(p, x2), 1.48572235717979e-05f);
    p = __fadd_rn(__fmul_rn(p, x2), 6.37261928875436e-04f);
    p = __fadd_rn(__fmul_rn(p, x2), 4.89352455891786e-03f);
    float num = __fmul_rn(xc, p);
    float q = 1.19825839466702e-06f;
    q = __fadd_rn(__fmul_rn(q, x2), 1.18534705686654e-04f);
    q = __fadd_rn(__fmul_rn(q, x2), 2.26843463243900e-03f);
    q = __fadd_rn(__fmul_rn(q, x2), 4.89352518554385e-03f);
    float r = __fdiv_rn(num, q);
    return (ax < 0.0004f) ? x : r;
}

// XLA LogisticExpander: logistic(x) = 0.5 + 0.5 * tanh(0.5 * x)
__device__ __forceinline__ float xla_sigmoid(float x) {
    return __fadd_rn(0.5f, __fmul_rn(0.5f, xla_tanh(__fmul_rn(0.5f, x))));
}

// correctly-rounded f32 log via double (immune to --use_fast_math logf demotion)
__device__ __forceinline__ float exact_logf(float x) {
    return (float)log((double)x);
}

// ---------------- E-table kernel: E[v][col] = emb[v] @ W_ih[:,col] ----------------
__global__ void ecomp_kernel(const float* __restrict__ emb, const float* __restrict__ W_ih) {
    int idx = blockIdx.x * blockDim.x + threadIdx.x;
    if (idx >= VOCAB * GATES) return;
    int v = idx / GATES, col = idx - v * GATES;
    float acc = 0.0f;
    for (int k = 0; k < HID; k++)
        acc = __fmaf_rn(emb[v * HID + k], W_ih[k * GATES + col], acc);
    g_E[idx] = acc;
}

// ---------------- Main persistent-per-CTA LSTM kernel ----------------
__global__ void __launch_bounds__(NTHREADS, 2)
rnn_main(const float* __restrict__ z,
         const float* __restrict__ W_lh, const float* __restrict__ b_lh,
         const float* __restrict__ W_lc, const float* __restrict__ b_lc,
         const float* __restrict__ W_hh,
         const float* __restrict__ b_ih, const float* __restrict__ b_hh,
         const float* __restrict__ W_out, const float* __restrict__ b_out,
         float* __restrict__ out, StepKeys keys)
{
    extern __shared__ float sm[];
    float* hbuf0   = sm + OFF_HA;      // hT[unit][row], PAD-strided
    float* hbuf1   = sm + OFF_HB;
    float* Esm     = sm + OFF_E;       // [5][1024]
    float* WoutSm  = sm + OFF_WOUT;    // [256][4]
    float* zsm     = sm + OFF_ZS;      // [32][128]
    float* boutSm  = sm + OFF_BOUT;    // [4]
    float* logitSm = sm + OFF_LOGIT;   // [32][4]
    int*   tokSm   = (int*)(sm + OFF_TOK);  // [32]

    const int tid = threadIdx.x;
    const int j   = tid;                     // hidden unit owned by this thread
    const int rowBase = blockIdx.x * TB;

    // cooperative SMEM fills
    for (int i = tid; i < VOCAB * GATES; i += NTHREADS) Esm[i] = g_E[i];
    for (int i = tid; i < HID * NUCV; i += NTHREADS)    WoutSm[i] = W_out[i];
    if (tid < NUCV) boutSm[tid] = b_out[tid];
    if (tid < TB)   tokSm[tid]  = SOS_TOK;
    for (int i = tid; i < TB * LATENT; i += NTHREADS)
        zsm[i] = z[(size_t)rowBase * LATENT + i];
    __syncthreads();

    // per-thread persistent cell state c[row] for unit j
    float creg[TB];

    // ---- prologue: h0 = tanh(z@W_lh + b_lh), c0 = tanh(z@W_lc + b_lc) ----
    {
        const float* wlh = W_lh + j;
        const float* wlc = W_lc + j;
        float blh = b_lh[j], blc = b_lc[j];
        #pragma unroll
        for (int ch = 0; ch < TB / CH; ch++) {
            float ah[CH], ac[CH];
            #pragma unroll
            for (int rr = 0; rr < CH; rr++) { ah[rr] = 0.0f; ac[rr] = 0.0f; }
            for (int k = 0; k < LATENT; k++) {
                float wh = wlh[k * HID];
                float wc = wlc[k * HID];
                #pragma unroll
                for (int rr = 0; rr < CH; rr++) {
                    float zv = zsm[(ch * CH + rr) * LATENT + k];
                    ah[rr] = __fmaf_rn(zv, wh, ah[rr]);
                    ac[rr] = __fmaf_rn(zv, wc, ac[rr]);
                }
            }
            #pragma unroll
            for (int rr = 0; rr < CH; rr++) {
                int r = ch * CH + rr;
                hbuf0[j * PAD + r] = xla_tanh(__fadd_rn(ah[rr], blh));
                creg[r]            = xla_tanh(__fadd_rn(ac[rr], blc));
            }
        }
    }
    __syncthreads();

    // loop-invariant biases for this unit's 4 gate columns
    float bih0 = b_ih[j],       bih1 = b_ih[256 + j];
    float bih2 = b_ih[512 + j], bih3 = b_ih[768 + j];
    float bhh0 = b_hh[j],       bhh1 = b_hh[256 + j];
    float bhh2 = b_hh[512 + j], bhh3 = b_hh[768 + j];

    float* hOld = hbuf0;
    float* hNew = hbuf1;
    const float* Wc = W_hh + j;   // column base for gate i; +256/+512/+768 for f/g/o

    for (int s = 0; s < SEQN; s++) {
        // ---- gates: acc = h @ W_hh (sequential k, FMA), 16-row sweeps ----
        #pragma unroll
        for (int ch = 0; ch < TB / CH; ch++) {
            float ai[CH], af_[CH], ag[CH], ao[CH];
            #pragma unroll
            for (int rr = 0; rr < CH; rr++) {
                ai[rr] = 0.0f; af_[rr] = 0.0f; ag[rr] = 0.0f; ao[rr] = 0.0f;
            }
            const float* hrow = hOld + ch * CH;
            #pragma unroll 2
            for (int k = 0; k < HID; k++) {
                float wi = Wc[(size_t)k * GATES];
                float wf = Wc[(size_t)k * GATES + 256];
                float wg = Wc[(size_t)k * GATES + 512];
                float wo = Wc[(size_t)k * GATES + 768];
                const float2* h2 = (const float2*)(hrow + k * PAD);
                #pragma unroll
                for (int rp = 0; rp < CH / 2; rp++) {
                    float2 hv = h2[rp];
                    ai [2*rp]   = __fmaf_rn(hv.x, wi, ai [2*rp]);
                    af_[2*rp]   = __fmaf_rn(hv.x, wf, af_[2*rp]);
                    ag [2*rp]   = __fmaf_rn(hv.x, wg, ag [2*rp]);
                    ao [2*rp]   = __fmaf_rn(hv.x, wo, ao [2*rp]);
                    ai [2*rp+1] = __fmaf_rn(hv.y, wi, ai [2*rp+1]);
                    af_[2*rp+1] = __fmaf_rn(hv.y, wf, af_[2*rp+1]);
                    ag [2*rp+1] = __fmaf_rn(hv.y, wg, ag [2*rp+1]);
                    ao [2*rp+1] = __fmaf_rn(hv.y, wo, ao [2*rp+1]);
                }
            }
            // ---- pointwise cell update; association matches ((xW+b_ih)+hW)+b_hh ----
            #pragma unroll
            for (int rr = 0; rr < CH; rr++) {
                int r = ch * CH + rr;
                int tok = tokSm[r];
                const float* Ev = Esm + tok * GATES + j;
                float gi = __fadd_rn(__fadd_rn(__fadd_rn(Ev[0],   bih0), ai [rr]), bhh0);
                float gf = __fadd_rn(__fadd_rn(__fadd_rn(Ev[256], bih1), af_[rr]), bhh1);
                float gg = __fadd_rn(__fadd_rn(__fadd_rn(Ev[512], bih2), ag [rr]), bhh2);
                float go = __fadd_rn(__fadd_rn(__fadd_rn(Ev[768], bih3), ao [rr]), bhh3);
                float iv = xla_sigmoid(gi);
                float fv = xla_sigmoid(gf);
                float gv = xla_tanh(gg);
                float ov = xla_sigmoid(go);
                float cc = __fadd_rn(__fmul_rn(fv, creg[r]), __fmul_rn(iv, gv));
                creg[r] = cc;
                hNew[j * PAD + r] = __fmul_rn(ov, xla_tanh(cc));
            }
        }
        __syncthreads();

        // ---- logits = h @ W_out + b_out (threads 0..127: one (row, nuc) each) ----
        if (tid < TB * NUCV) {
            int r = tid >> 2, n = tid & 3;
            float acc = 0.0f;
            for (int k = 0; k < HID; k++)
                acc = __fmaf_rn(hNew[k * PAD + r], WoutSm[k * NUCV + n], acc);
            float lg = __fadd_rn(acc, boutSm[n]);
            logitSm[tid] = lg;
            size_t b = (size_t)(rowBase + r);
            out[(b * SEQN + s) * NUCV + n] = lg;
        }
        __syncthreads();

        // ---- exact jax.random.categorical, partitionable Threefry ----
        // _threefry_random_bits_partitionable: counter = (hi, lo) of 64-bit
        // flat index (idx = b*4+n < 2^32 => (0, idx)); for bit_width==32 the
        // two threefry outputs are XOR-folded: bits = o0 ^ o1.
        if (tid < TB) {
            int r = tid;
            int b = rowBase + r;
            unsigned base = (unsigned)b * (unsigned)NUCV;
            float best = -3.402823466e+38f;
            int bestn = 0;
            #pragma unroll
            for (int n = 0; n < NUCV; n++) {
                unsigned o0, o1;
                tf2x32(keys.k0[s], keys.k1[s], 0u, base + (unsigned)n, o0, o1);
                unsigned bits = o0 ^ o1;
                unsigned fb = (bits >> 9) | 0x3f800000u;
                float u = __fadd_rn(__uint_as_float(fb), -1.0f);
                u = fmaxf(u, 1.17549435e-38f);              // minval = tiny
                float lu  = exact_logf(u);                  // log(u) < 0
                float gum = -exact_logf(-lu);               // gumbel
                float v = __fadd_rn(gum, logitSm[r * NUCV + n]);
                if (v > best) { best = v; bestn = n; }      // first-max tie-break
            }
            tokSm[r] = bestn;
            // checker reads the index region as float32 -> write float values
            out[(size_t)BATCH * SEQN * NUCV + (size_t)b * SEQN + s] = (float)bestn;
        }
        __syncthreads();

        float* t = hOld; hOld = hNew; hNew = t;
    }
}

extern "C" void kernel_launch(void* const* d_in, const int* in_sizes, int n_in,
                              void* d_out, int out_size) {
    (void)in_sizes; (void)n_in; (void)out_size;
    const float* z     = (const float*)d_in[0];
    const float* W_lh  = (const float*)d_in[1];
    const float* b_lh  = (const float*)d_in[2];
    const float* W_lc  = (const float*)d_in[3];
    const float* b_lc  = (const float*)d_in[4];
    const float* emb   = (const float*)d_in[5];
    const float* W_ih  = (const float*)d_in[6];
    const float* W_hh  = (const float*)d_in[7];
    const float* b_ih  = (const float*)d_in[8];
    const float* b_hh  = (const float*)d_in[9];
    const float* W_out = (const float*)d_in[10];
    const float* b_out = (const float*)d_in[11];
    float* out = (float*)d_out;

    // jax.random.split(key(42), 50), threefry_partitionable (foldlike):
    // subkey_s = threefry((0,42), counter=(0, s)) -> (o0, o1)
    StepKeys keys;
    for (int s = 0; s < SEQN; s++) {
        unsigned o0, o1;
        tf2x32(0u, 42u, 0u, (unsigned)s, o0, o1);
        keys.k0[s] = o0;
        keys.k1[s] = o1;
    }

    ecomp_kernel<<<(VOCAB * GATES + 255) / 256, 256>>>(emb, W_ih);

    cudaFuncSetAttribute(rnn_main, cudaFuncAttributeMaxDynamicSharedMemorySize, SMEM_BYTES);
    rnn_main<<<BATCH / TB, NTHREADS, SMEM_BYTES>>>(
        z, W_lh, b_lh, W_lc, b_lc, W_hh, b_ih, b_hh, W_out, b_out, out, keys);
}

// round 11
// speedup vs baseline: 1.1393x; 1.1393x over previous
#include <cuda_runtime.h>
#include <cstdint>

#define BATCH   65536
#define LATENT  128
#define HID     256
#define GATES   1024
#define SEQN    50
#define NUCV    4
#define VOCAB   5
#define SOS_TOK 4

#define TB       32            // rows per CTA
#define CH       16            // rows per accumulation sweep
#define NTHREADS 256
#define PAD      34            // hT row padding (floats, even -> 8B aligned pairs)

// SMEM layout (float offsets)
#define OFF_HA    0
#define OFF_HB    8704         // 256*PAD
#define OFF_E     17408
#define OFF_WOUT  22528
#define OFF_ZS    23552
#define OFF_BOUT  27648
#define OFF_TOK   27652
#define SMEM_FLOATS 27684
#define SMEM_BYTES  (SMEM_FLOATS * 4)

struct StepKeys { unsigned int k0[SEQN]; unsigned int k1[SEQN]; };

__device__ float g_E[VOCAB * GATES];   // precomputed emb[v] @ W_ih (no biases)

// ---------------- packed f32x2 helpers (Blackwell sm_103a) ----------------
__device__ __forceinline__ unsigned long long pack2(float lo, float hi) {
    unsigned long long r;
    asm("mov.b64 %0, {%1, %2};" : "=l"(r) : "f"(lo), "f"(hi));
    return r;
}
__device__ __forceinline__ void unpack2(unsigned long long v, float& lo, float& hi) {
    asm("mov.b64 {%0, %1}, %2;" : "=f"(lo), "=f"(hi) : "l"(v));
}
// per-lane IEEE RN fused multiply-add on packed 2xf32 — bit-identical to
// two scalar __fmaf_rn per lane
__device__ __forceinline__ unsigned long long fma2(unsigned long long a,
                                                   unsigned long long b,
                                                   unsigned long long c) {
    unsigned long long d;
    asm("fma.rn.f32x2 %0, %1, %2, %3;" : "=l"(d) : "l"(a), "l"(b), "l"(c));
    return d;
}

// ---------------- Threefry-2x32 (matches jax/_src/prng.py) ----------------
__host__ __device__ __forceinline__ unsigned int rotl32(unsigned int x, int d) {
    return (x << d) | (x >> (32 - d));
}

__host__ __device__ __forceinline__ void tf2x32(unsigned int k0, unsigned int k1,
                                                unsigned int x0, unsigned int x1,
                                                unsigned int& o0, unsigned int& o1)
{
    unsigned int k2 = k0 ^ k1 ^ 0x1BD11BDAu;
    x0 += k0; x1 += k1;
    x0 += x1; x1 = rotl32(x1, 13); x1 ^= x0;
    x0 += x1; x1 = rotl32(x1, 15); x1 ^= x0;
    x0 += x1; x1 = rotl32(x1, 26); x1 ^= x0;
    x0 += x1; x1 = rotl32(x1, 6);  x1 ^= x0;
    x0 += k1; x1 += k2 + 1u;
    x0 += x1; x1 = rotl32(x1, 17); x1 ^= x0;
    x0 += x1; x1 = rotl32(x1, 29); x1 ^= x0;
    x0 += x1; x1 = rotl32(x1, 16); x1 ^= x0;
    x0 += x1; x1 = rotl32(x1, 24); x1 ^= x0;
    x0 += k2; x1 += k0 + 2u;
    x0 += x1; x1 = rotl32(x1, 13); x1 ^= x0;
    x0 += x1; x1 = rotl32(x1, 15); x1 ^= x0;
    x0 += x1; x1 = rotl32(x1, 26); x1 ^= x0;
    x0 += x1; x1 = rotl32(x1, 6);  x1 ^= x0;
    x0 += k0; x1 += k1 + 3u;
    x0 += x1; x1 = rotl32(x1, 17); x1 ^= x0;
    x0 += x1; x1 = rotl32(x1, 29); x1 ^= x0;
    x0 += x1; x1 = rotl32(x1, 16); x1 ^= x0;
    x0 += x1; x1 = rotl32(x1, 24); x1 ^= x0;
    x0 += k1; x1 += k2 + 4u;
    x0 += x1; x1 = rotl32(x1, 13); x1 ^= x0;
    x0 += x1; x1 = rotl32(x1, 15); x1 ^= x0;
    x0 += x1; x1 = rotl32(x1, 26); x1 ^= x0;
    x0 += x1; x1 = rotl32(x1, 6);  x1 ^= x0;
    x0 += k2; x1 += k0 + 5u;
    o0 = x0; o1 = x1;
}

// ---------------- XLA-exact activations ----------------
__device__ __forceinline__ float xla_tanh(float x) {
    float ax = fabsf(x);
    float xc = fminf(fmaxf(x, -7.90531110763549805f), 7.90531110763549805f);
    float x2 = __fmul_rn(xc, xc);
    float p = -2.76076847742355e-16f;
    p = __fadd_rn(__fmul_rn(p, x2), 2.00018790482477e-13f);
    p = __fadd_rn(__fmul_rn(p, x2), -8.60467152213735e-11f);
    p = __fadd_rn(__fmul_rn(p, x2), 5.12229709037114e-08f);
    p = __fadd_rn(__fmul_rn(p, x2), 1.48572235717979e-05f);
    p = __fadd_rn(__fmul_rn(p, x2), 6.37261928875436e-04f);
    p = __fadd_rn(__fmul_rn(p, x2), 4.89352455891786e-03f);
    float num = __fmul_rn(xc, p);
    float q = 1.19825839466702e-06f;
    q = __fadd_rn(__fmul_rn(q, x2), 1.18534705686654e-04f);
    q = __fadd_rn(__fmul_rn(q, x2), 2.26843463243900e-03f);
    q = __fadd_rn(__fmul_rn(q, x2), 4.89352518554385e-03f);
    float r = __fdiv_rn(num, q);
    return (ax < 0.0004f) ? x : r;
}

__device__ __forceinline__ float xla_sigmoid(float x) {
    return __fadd_rn(0.5f, __fmul_rn(0.5f, xla_tanh(__fmul_rn(0.5f, x))));
}

// correctly-rounded f32 log via double (immune to fast-math logf demotion)
__device__ __forceinline__ float exact_logf(float x) {
    return (float)log((double)x);
}

// ---------------- E-table kernel: E[v][col] = emb[v] @ W_ih[:,col] ----------------
__global__ void ecomp_kernel(const float* __restrict__ emb, const float* __restrict__ W_ih) {
    int idx = blockIdx.x * blockDim.x + threadIdx.x;
    if (idx >= VOCAB * GATES) return;
    int v = idx / GATES, col = idx - v * GATES;
    float acc = 0.0f;
    for (int k = 0; k < HID; k++)
        acc = __fmaf_rn(emb[v * HID + k], W_ih[k * GATES + col], acc);
    g_E[idx] = acc;
}

// ---------------- Main persistent-per-CTA LSTM kernel ----------------
__global__ void __launch_bounds__(NTHREADS, 2)
rnn_main(const float* __restrict__ z,
         const float* __restrict__ W_lh, const float* __restrict__ b_lh,
         const float* __restrict__ W_lc, const float* __restrict__ b_lc,
         const float* __restrict__ W_hh,
         const float* __restrict__ b_ih, const float* __restrict__ b_hh,
         const float* __restrict__ W_out, const float* __restrict__ b_out,
         float* __restrict__ out, StepKeys keys)
{
    extern __shared__ float sm[];
    float* hbuf0   = sm + OFF_HA;      // hT[unit][row], PAD-strided
    float* hbuf1   = sm + OFF_HB;
    float* Esm     = sm + OFF_E;       // [5][1024]
    float* WoutSm  = sm + OFF_WOUT;    // [256][4]
    float* zsm     = sm + OFF_ZS;      // [32][128]
    float* boutSm  = sm + OFF_BOUT;    // [4]
    int*   tokSm   = (int*)(sm + OFF_TOK);  // [32]

    const int tid = threadIdx.x;
    const int j   = tid;                     // hidden unit owned by this thread
    const int rowBase = blockIdx.x * TB;

    // cooperative SMEM fills
    for (int i = tid; i < VOCAB * GATES; i += NTHREADS) Esm[i] = g_E[i];
    for (int i = tid; i < HID * NUCV; i += NTHREADS)    WoutSm[i] = W_out[i];
    if (tid < NUCV) boutSm[tid] = b_out[tid];
    if (tid < TB)   tokSm[tid]  = SOS_TOK;
    for (int i = tid; i < TB * LATENT; i += NTHREADS)
        zsm[i] = z[(size_t)rowBase * LATENT + i];
    __syncthreads();

    // per-thread persistent cell state c[row] for unit j
    float creg[TB];

    // ---- prologue: h0 = tanh(z@W_lh + b_lh), c0 = tanh(z@W_lc + b_lc) ----
    {
        const float* wlh = W_lh + j;
        const float* wlc = W_lc + j;
        float blh = b_lh[j], blc = b_lc[j];
        #pragma unroll
        for (int ch = 0; ch < TB / CH; ch++) {
            float ah[CH], ac[CH];
            #pragma unroll
            for (int rr = 0; rr < CH; rr++) { ah[rr] = 0.0f; ac[rr] = 0.0f; }
            for (int k = 0; k < LATENT; k++) {
                float wh = wlh[k * HID];
                float wc = wlc[k * HID];
                #pragma unroll
                for (int rr = 0; rr < CH; rr++) {
                    float zv = zsm[(ch * CH + rr) * LATENT + k];
                    ah[rr] = __fmaf_rn(zv, wh, ah[rr]);
                    ac[rr] = __fmaf_rn(zv, wc, ac[rr]);
                }
            }
            #pragma unroll
            for (int rr = 0; rr < CH; rr++) {
                int r = ch * CH + rr;
                hbuf0[j * PAD + r] = xla_tanh(__fadd_rn(ah[rr], blh));
                creg[r]            = xla_tanh(__fadd_rn(ac[rr], blc));
            }
        }
    }
    __syncthreads();

    // loop-invariant biases for this unit's 4 gate columns
    float bih0 = b_ih[j],       bih1 = b_ih[256 + j];
    float bih2 = b_ih[512 + j], bih3 = b_ih[768 + j];
    float bhh0 = b_hh[j],       bhh1 = b_hh[256 + j];
    float bhh2 = b_hh[512 + j], bhh3 = b_hh[768 + j];

    float* hOld = hbuf0;
    float* hNew = hbuf1;
    const float* Wc = W_hh + j;   // column base for gate i; +256/+512/+768 for f/g/o

    for (int s = 0; s < SEQN; s++) {
        // ---- gates: acc = h @ W_hh via packed fma.rn.f32x2 (row pairs) ----
        #pragma unroll
        for (int ch = 0; ch < TB / CH; ch++) {
            unsigned long long ai[CH/2], af_[CH/2], ag[CH/2], ao[CH/2];
            #pragma unroll
            for (int rp = 0; rp < CH/2; rp++) {
                ai[rp] = 0ULL; af_[rp] = 0ULL; ag[rp] = 0ULL; ao[rp] = 0ULL;
            }
            const float* hrow = hOld + ch * CH;
            #pragma unroll 2
            for (int k = 0; k < HID; k++) {
                float wi = Wc[(size_t)k * GATES];
                float wf = Wc[(size_t)k * GATES + 256];
                float wg = Wc[(size_t)k * GATES + 512];
                float wo = Wc[(size_t)k * GATES + 768];
                unsigned long long wi2 = pack2(wi, wi);
                unsigned long long wf2 = pack2(wf, wf);
                unsigned long long wg2 = pack2(wg, wg);
                unsigned long long wo2 = pack2(wo, wo);
                // SMEM float pair IS the packed f32x2 operand (lo = even row)
                const unsigned long long* h2 =
                    (const unsigned long long*)(hrow + k * PAD);
                #pragma unroll
                for (int rp = 0; rp < CH / 2; rp++) {
                    unsigned long long hv = h2[rp];
                    ai [rp] = fma2(hv, wi2, ai [rp]);
                    af_[rp] = fma2(hv, wf2, af_[rp]);
                    ag [rp] = fma2(hv, wg2, ag [rp]);
                    ao [rp] = fma2(hv, wo2, ao [rp]);
                }
            }
            // ---- pointwise cell update; association matches ((xW+b_ih)+hW)+b_hh ----
            #pragma unroll
            for (int rp = 0; rp < CH / 2; rp++) {
                float aiL, aiH, afL, afH, agL, agH, aoL, aoH;
                unpack2(ai [rp], aiL, aiH);
                unpack2(af_[rp], afL, afH);
                unpack2(ag [rp], agL, agH);
                unpack2(ao [rp], aoL, aoH);
                #pragma unroll
                for (int lane = 0; lane < 2; lane++) {
                    int r = ch * CH + 2 * rp + lane;
                    float aI = lane ? aiH : aiL;
                    float aF = lane ? afH : afL;
                    float aG = lane ? agH : agL;
                    float aO = lane ? aoH : aoL;
                    int tok = tokSm[r];
                    const float* Ev = Esm + tok * GATES + j;
                    float gi = __fadd_rn(__fadd_rn(__fadd_rn(Ev[0],   bih0), aI), bhh0);
                    float gf = __fadd_rn(__fadd_rn(__fadd_rn(Ev[256], bih1), aF), bhh1);
                    float gg = __fadd_rn(__fadd_rn(__fadd_rn(Ev[512], bih2), aG), bhh2);
                    float go = __fadd_rn(__fadd_rn(__fadd_rn(Ev[768], bih3), aO), bhh3);
                    float iv = xla_sigmoid(gi);
                    float fv = xla_sigmoid(gf);
                    float gv = xla_tanh(gg);
                    float ov = xla_sigmoid(go);
                    float cc = __fadd_rn(__fmul_rn(fv, creg[r]), __fmul_rn(iv, gv));
                    creg[r] = cc;
                    hNew[j * PAD + r] = __fmul_rn(ov, xla_tanh(cc));
                }
            }
        }
        __syncthreads();

        // ---- merged logits + exact categorical sampling (128 threads) ----
        // logits = h @ W_out + b_out; bits = o0 ^ o1 of partitionable
        // threefry with counter (0, b*4+n); gumbel = -log(-log(u));
        // 4-lane shfl argmax with first-max tie-break.
        if (tid < TB * NUCV) {
            int r = tid >> 2, n = tid & 3;
            float acc = 0.0f;
            for (int k = 0; k < HID; k++)
                acc = __fmaf_rn(hNew[k * PAD + r], WoutSm[k * NUCV + n], acc);
            float lg = __fadd_rn(acc, boutSm[n]);
            size_t b = (size_t)(rowBase + r);
            out[(b * SEQN + s) * NUCV + n] = lg;

            unsigned o0, o1;
            tf2x32(keys.k0[s], keys.k1[s], 0u,
                   (unsigned)b * (unsigned)NUCV + (unsigned)n, o0, o1);
            unsigned bits = o0 ^ o1;
            unsigned fb = (bits >> 9) | 0x3f800000u;
            float u = __fadd_rn(__uint_as_float(fb), -1.0f);
            u = fmaxf(u, 1.17549435e-38f);              // minval = tiny
            float lu  = exact_logf(u);
            float gum = -exact_logf(-lu);
            float v = __fadd_rn(gum, lg);

            float bv = v; int bn = n;
            #pragma unroll
            for (int m = 1; m < 4; m <<= 1) {
                float ov = __shfl_xor_sync(0xffffffffu, bv, m);
                int   on = __shfl_xor_sync(0xffffffffu, bn, m);
                if (ov > bv || (ov == bv && on < bn)) { bv = ov; bn = on; }
            }
            if (n == 0) {
                tokSm[r] = bn;
                out[(size_t)BATCH * SEQN * NUCV + b * SEQN + s] = (float)bn;
            }
        }
        __syncthreads();

        float* t = hOld; hOld = hNew; hNew = t;
    }
}

extern "C" void kernel_launch(void* const* d_in, const int* in_sizes, int n_in,
                              void* d_out, int out_size) {
    (void)in_sizes; (void)n_in; (void)out_size;
    const float* z     = (const float*)d_in[0];
    const float* W_lh  = (const float*)d_in[1];
    const float* b_lh  = (const float*)d_in[2];
    const float* W_lc  = (const float*)d_in[3];
    const float* b_lc  = (const float*)d_in[4];
    const float* emb   = (const float*)d_in[5];
    const float* W_ih  = (const float*)d_in[6];
    const float* W_hh  = (const float*)d_in[7];
    const float* b_ih  = (const float*)d_in[8];
    const float* b_hh  = (const float*)d_in[9];
    const float* W_out = (const float*)d_in[10];
    const float* b_out = (const float*)d_in[11];
    float* out = (float*)d_out;

    // jax.random.split(key(42), 50), threefry_partitionable (foldlike):
    // subkey_s = threefry((0,42), counter=(0, s)) -> (o0, o1)
    StepKeys keys;
    for (int s = 0; s < SEQN; s++) {
        unsigned o0, o1;
        tf2x32(0u, 42u, 0u, (unsigned)s, o0, o1);
        keys.k0[s] = o0;
        keys.k1[s] = o1;
    }

    ecomp_kernel<<<(VOCAB * GATES + 255) / 256, 256>>>(emb, W_ih);

    cudaFuncSetAttribute(rnn_main, cudaFuncAttributeMaxDynamicSharedMemorySize, SMEM_BYTES);
    rnn_main<<<BATCH / TB, NTHREADS, SMEM_BYTES>>>(
        z, W_lh, b_lh, W_lc, b_lc, W_hh, b_ih, b_hh, W_out, b_out, out, keys);
}

// round 12
// speedup vs baseline: 1.4114x; 1.2388x over previous
#include <cuda_runtime.h>
#include <cstdint>

#define BATCH   65536
#define LATENT  128
#define HID     256
#define GATES   1024
#define SEQN    50
#define NUCV    4
#define VOCAB   5
#define SOS_TOK 4

#define TB       32            // rows per CTA
#define CH       16            // rows per accumulation sweep
#define NTHREADS 256
#define PAD      36            // hT row stride: 144B = 16B-aligned for LDS.128

// SMEM layout (float offsets)
#define OFF_HA    0
#define OFF_HB    9216         // 256*PAD
#define OFF_E     18432
#define OFF_WOUT  23552
#define OFF_ZS    24576
#define OFF_BOUT  28672
#define OFF_TOK   28676
#define SMEM_FLOATS 28708
#define SMEM_BYTES  (SMEM_FLOATS * 4)

struct StepKeys { unsigned int k0[SEQN]; unsigned int k1[SEQN]; };

__device__ float  g_E[VOCAB * GATES];        // precomputed emb[v] @ W_ih
__device__ float4 g_Wp[(HID + 1) * HID];     // repacked W_hh: [k][j] = (wi,wf,wg,wo); +1 row for prefetch overread

// ---------------- packed f32x2 helpers (Blackwell sm_103a) ----------------
__device__ __forceinline__ unsigned long long pack2(float lo, float hi) {
    unsigned long long r;
    asm("mov.b64 %0, {%1, %2};" : "=l"(r) : "f"(lo), "f"(hi));
    return r;
}
__device__ __forceinline__ void unpack2(unsigned long long v, float& lo, float& hi) {
    asm("mov.b64 {%0, %1}, %2;" : "=f"(lo), "=f"(hi) : "l"(v));
}
// per-lane IEEE RN fused multiply-add on packed 2xf32 — bit-identical to
// two scalar __fmaf_rn per lane
__device__ __forceinline__ unsigned long long fma2(unsigned long long a,
                                                   unsigned long long b,
                                                   unsigned long long c) {
    unsigned long long d;
    asm("fma.rn.f32x2 %0, %1, %2, %3;" : "=l"(d) : "l"(a), "l"(b), "l"(c));
    return d;
}

// ---------------- Threefry-2x32 (matches jax/_src/prng.py) ----------------
__host__ __device__ __forceinline__ unsigned int rotl32(unsigned int x, int d) {
    return (x << d) | (x >> (32 - d));
}

__host__ __device__ __forceinline__ void tf2x32(unsigned int k0, unsigned int k1,
                                                unsigned int x0, unsigned int x1,
                                                unsigned int& o0, unsigned int& o1)
{
    unsigned int k2 = k0 ^ k1 ^ 0x1BD11BDAu;
    x0 += k0; x1 += k1;
    x0 += x1; x1 = rotl32(x1, 13); x1 ^= x0;
    x0 += x1; x1 = rotl32(x1, 15); x1 ^= x0;
    x0 += x1; x1 = rotl32(x1, 26); x1 ^= x0;
    x0 += x1; x1 = rotl32(x1, 6);  x1 ^= x0;
    x0 += k1; x1 += k2 + 1u;
    x0 += x1; x1 = rotl32(x1, 17); x1 ^= x0;
    x0 += x1; x1 = rotl32(x1, 29); x1 ^= x0;
    x0 += x1; x1 = rotl32(x1, 16); x1 ^= x0;
    x0 += x1; x1 = rotl32(x1, 24); x1 ^= x0;
    x0 += k2; x1 += k0 + 2u;
    x0 += x1; x1 = rotl32(x1, 13); x1 ^= x0;
    x0 += x1; x1 = rotl32(x1, 15); x1 ^= x0;
    x0 += x1; x1 = rotl32(x1, 26); x1 ^= x0;
    x0 += x1; x1 = rotl32(x1, 6);  x1 ^= x0;
    x0 += k0; x1 += k1 + 3u;
    x0 += x1; x1 = rotl32(x1, 17); x1 ^= x0;
    x0 += x1; x1 = rotl32(x1, 29); x1 ^= x0;
    x0 += x1; x1 = rotl32(x1, 16); x1 ^= x0;
    x0 += x1; x1 = rotl32(x1, 24); x1 ^= x0;
    x0 += k1; x1 += k2 + 4u;
    x0 += x1; x1 = rotl32(x1, 13); x1 ^= x0;
    x0 += x1; x1 = rotl32(x1, 15); x1 ^= x0;
    x0 += x1; x1 = rotl32(x1, 26); x1 ^= x0;
    x0 += x1; x1 = rotl32(x1, 6);  x1 ^= x0;
    x0 += k2; x1 += k0 + 5u;
    o0 = x0; o1 = x1;
}

// ---------------- XLA-exact activations ----------------
__device__ __forceinline__ float xla_tanh(float x) {
    float ax = fabsf(x);
    float xc = fminf(fmaxf(x, -7.90531110763549805f), 7.90531110763549805f);
    float x2 = __fmul_rn(xc, xc);
    float p = -2.76076847742355e-16f;
    p = __fadd_rn(__fmul_rn(p, x2), 2.00018790482477e-13f);
    p = __fadd_rn(__fmul_rn(p, x2), -8.60467152213735e-11f);
    p = __fadd_rn(__fmul_rn(p, x2), 5.12229709037114e-08f);
    p = __fadd_rn(__fmul_rn(p, x2), 1.48572235717979e-05f);
    p = __fadd_rn(__fmul_rn(p, x2), 6.37261928875436e-04f);
    p = __fadd_rn(__fmul_rn(p, x2), 4.89352455891786e-03f);
    float num = __fmul_rn(xc, p);
    float q = 1.19825839466702e-06f;
    q = __fadd_rn(__fmul_rn(q, x2), 1.18534705686654e-04f);
    q = __fadd_rn(__fmul_rn(q, x2), 2.26843463243900e-03f);
    q = __fadd_rn(__fmul_rn(q, x2), 4.89352518554385e-03f);
    float r = __fdiv_rn(num, q);
    return (ax < 0.0004f) ? x : r;
}

__device__ __forceinline__ float xla_sigmoid(float x) {
    return __fadd_rn(0.5f, __fmul_rn(0.5f, xla_tanh(__fmul_rn(0.5f, x))));
}

// correctly-rounded f32 log via double (immune to fast-math logf demotion)
__device__ __forceinline__ float exact_logf(float x) {
    return (float)log((double)x);
}

// ---------------- E-table kernel: E[v][col] = emb[v] @ W_ih[:,col] ----------------
__global__ void ecomp_kernel(const float* __restrict__ emb, const float* __restrict__ W_ih) {
    int idx = blockIdx.x * blockDim.x + threadIdx.x;
    if (idx >= VOCAB * GATES) return;
    int v = idx / GATES, col = idx - v * GATES;
    float acc = 0.0f;
    for (int k = 0; k < HID; k++)
        acc = __fmaf_rn(emb[v * HID + k], W_ih[k * GATES + col], acc);
    g_E[idx] = acc;
}

// ---------------- W repack kernel: g_Wp[k][j] = (wi,wf,wg,wo) ----------------
__global__ void wpack_kernel(const float* __restrict__ W_hh) {
    int idx = blockIdx.x * blockDim.x + threadIdx.x;
    if (idx >= (HID + 1) * HID) return;
    int k = idx >> 8, j = idx & (HID - 1);
    float4 w;
    if (k < HID) {
        w.x = W_hh[(size_t)k * GATES + j];
        w.y = W_hh[(size_t)k * GATES + 256 + j];
        w.z = W_hh[(size_t)k * GATES + 512 + j];
        w.w = W_hh[(size_t)k * GATES + 768 + j];
    } else {
        w.x = w.y = w.z = w.w = 0.0f;   // prefetch overread row
    }
    g_Wp[idx] = w;
}

// ---------------- Main persistent-per-CTA LSTM kernel ----------------
__global__ void __launch_bounds__(NTHREADS, 2)
rnn_main(const float* __restrict__ z,
         const float* __restrict__ W_lh, const float* __restrict__ b_lh,
         const float* __restrict__ W_lc, const float* __restrict__ b_lc,
         const float* __restrict__ b_ih, const float* __restrict__ b_hh,
         const float* __restrict__ W_out, const float* __restrict__ b_out,
         float* __restrict__ out, StepKeys keys)
{
    extern __shared__ float sm[];
    float* hbuf0   = sm + OFF_HA;      // hT[unit][row], PAD-strided
    float* hbuf1   = sm + OFF_HB;
    float* Esm     = sm + OFF_E;       // [5][1024]
    float* WoutSm  = sm + OFF_WOUT;    // [256][4]
    float* zsm     = sm + OFF_ZS;      // [32][128]
    float* boutSm  = sm + OFF_BOUT;    // [4]
    int*   tokSm   = (int*)(sm + OFF_TOK);  // [32]

    const int tid = threadIdx.x;
    const int j   = tid;                     // hidden unit owned by this thread
    const int rowBase = blockIdx.x * TB;

    // cooperative SMEM fills
    for (int i = tid; i < VOCAB * GATES; i += NTHREADS) Esm[i] = g_E[i];
    for (int i = tid; i < HID * NUCV; i += NTHREADS)    WoutSm[i] = W_out[i];
    if (tid < NUCV) boutSm[tid] = b_out[tid];
    if (tid < TB)   tokSm[tid]  = SOS_TOK;
    for (int i = tid; i < TB * LATENT; i += NTHREADS)
        zsm[i] = z[(size_t)rowBase * LATENT + i];
    __syncthreads();

    // per-thread persistent cell state c[row] for unit j
    float creg[TB];

    // ---- prologue: h0 = tanh(z@W_lh + b_lh), c0 = tanh(z@W_lc + b_lc) ----
    {
        const float* wlh = W_lh + j;
        const float* wlc = W_lc + j;
        float blh = b_lh[j], blc = b_lc[j];
        #pragma unroll
        for (int ch = 0; ch < TB / CH; ch++) {
            float ah[CH], ac[CH];
            #pragma unroll
            for (int rr = 0; rr < CH; rr++) { ah[rr] = 0.0f; ac[rr] = 0.0f; }
            for (int k = 0; k < LATENT; k++) {
                float wh = wlh[k * HID];
                float wc = wlc[k * HID];
                #pragma unroll
                for (int rr = 0; rr < CH; rr++) {
                    float zv = zsm[(ch * CH + rr) * LATENT + k];
                    ah[rr] = __fmaf_rn(zv, wh, ah[rr]);
                    ac[rr] = __fmaf_rn(zv, wc, ac[rr]);
                }
            }
            #pragma unroll
            for (int rr = 0; rr < CH; rr++) {
                int r = ch * CH + rr;
                hbuf0[j * PAD + r] = xla_tanh(__fadd_rn(ah[rr], blh));
                creg[r]            = xla_tanh(__fadd_rn(ac[rr], blc));
            }
        }
    }
    __syncthreads();

    // loop-invariant biases for this unit's 4 gate columns
    float bih0 = b_ih[j],       bih1 = b_ih[256 + j];
    float bih2 = b_ih[512 + j], bih3 = b_ih[768 + j];
    float bhh0 = b_hh[j],       bhh1 = b_hh[256 + j];
    float bhh2 = b_hh[512 + j], bhh3 = b_hh[768 + j];

    float* hOld = hbuf0;
    float* hNew = hbuf1;
    const float4* __restrict__ Wp = g_Wp + j;   // [k][j], stride HID per k

    for (int s = 0; s < SEQN; s++) {
        // ---- gates: acc = h @ W_hh via packed fma.rn.f32x2, W prefetched ----
        #pragma unroll
        for (int ch = 0; ch < TB / CH; ch++) {
            unsigned long long ai[CH/2], af_[CH/2], ag[CH/2], ao[CH/2];
            #pragma unroll
            for (int rp = 0; rp < CH/2; rp++) {
                ai[rp] = 0ULL; af_[rp] = 0ULL; ag[rp] = 0ULL; ao[rp] = 0ULL;
            }
            const float* hrow = hOld + ch * CH;
            float4 wc = Wp[0];
            #pragma unroll 4
            for (int k = 0; k < HID; k++) {
                float4 wn = Wp[(k + 1) * HID];      // one-deep prefetch (overread row is padded)
                unsigned long long wi2 = pack2(wc.x, wc.x);
                unsigned long long wf2 = pack2(wc.y, wc.y);
                unsigned long long wg2 = pack2(wc.z, wc.z);
                unsigned long long wo2 = pack2(wc.w, wc.w);
                // 16 consecutive floats = 4x LDS.128 (broadcast, conflict-free)
                const ulonglong2* h4 = (const ulonglong2*)(hrow + k * PAD);
                #pragma unroll
                for (int q = 0; q < CH / 4; q++) {
                    ulonglong2 hp = h4[q];
                    ai [2*q]   = fma2(hp.x, wi2, ai [2*q]);
                    af_[2*q]   = fma2(hp.x, wf2, af_[2*q]);
                    ag [2*q]   = fma2(hp.x, wg2, ag [2*q]);
                    ao [2*q]   = fma2(hp.x, wo2, ao [2*q]);
                    ai [2*q+1] = fma2(hp.y, wi2, ai [2*q+1]);
                    af_[2*q+1] = fma2(hp.y, wf2, af_[2*q+1]);
                    ag [2*q+1] = fma2(hp.y, wg2, ag [2*q+1]);
                    ao [2*q+1] = fma2(hp.y, wo2, ao [2*q+1]);
                }
                wc = wn;
            }
            // ---- pointwise cell update; association matches ((xW+b_ih)+hW)+b_hh ----
            #pragma unroll
            for (int rp = 0; rp < CH / 2; rp++) {
                float aiL, aiH, afL, afH, agL, agH, aoL, aoH;
                unpack2(ai [rp], aiL, aiH);
                unpack2(af_[rp], afL, afH);
                unpack2(ag [rp], agL, agH);
                unpack2(ao [rp], aoL, aoH);
                #pragma unroll
                for (int lane = 0; lane < 2; lane++) {
                    int r = ch * CH + 2 * rp + lane;
                    float aI = lane ? aiH : aiL;
                    float aF = lane ? afH : afL;
                    float aG = lane ? agH : agL;
                    float aO = lane ? aoH : aoL;
                    int tok = tokSm[r];
                    const float* Ev = Esm + tok * GATES + j;
                    float gi = __fadd_rn(__fadd_rn(__fadd_rn(Ev[0],   bih0), aI), bhh0);
                    float gf = __fadd_rn(__fadd_rn(__fadd_rn(Ev[256], bih1), aF), bhh1);
                    float gg = __fadd_rn(__fadd_rn(__fadd_rn(Ev[512], bih2), aG), bhh2);
                    float go = __fadd_rn(__fadd_rn(__fadd_rn(Ev[768], bih3), aO), bhh3);
                    float iv = xla_sigmoid(gi);
                    float fv = xla_sigmoid(gf);
                    float gv = xla_tanh(gg);
                    float ov = xla_sigmoid(go);
                    float cc = __fadd_rn(__fmul_rn(fv, creg[r]), __fmul_rn(iv, gv));
                    creg[r] = cc;
                    hNew[j * PAD + r] = __fmul_rn(ov, xla_tanh(cc));
                }
            }
        }
        __syncthreads();

        // ---- merged logits + exact categorical sampling (128 threads) ----
        if (tid < TB * NUCV) {
            int r = tid >> 2, n = tid & 3;
            float acc = 0.0f;
            for (int k = 0; k < HID; k++)
                acc = __fmaf_rn(hNew[k * PAD + r], WoutSm[k * NUCV + n], acc);
            float lg = __fadd_rn(acc, boutSm[n]);
            size_t b = (size_t)(rowBase + r);
            out[(b * SEQN + s) * NUCV + n] = lg;

            unsigned o0, o1;
            tf2x32(keys.k0[s], keys.k1[s], 0u,
                   (unsigned)b * (unsigned)NUCV + (unsigned)n, o0, o1);
            unsigned bits = o0 ^ o1;
            unsigned fb = (bits >> 9) | 0x3f800000u;
            float u = __fadd_rn(__uint_as_float(fb), -1.0f);
            u = fmaxf(u, 1.17549435e-38f);              // minval = tiny
            float lu  = exact_logf(u);
            float gum = -exact_logf(-lu);
            float v = __fadd_rn(gum, lg);

            float bv = v; int bn = n;
            #pragma unroll
            for (int m = 1; m < 4; m <<= 1) {
                float ov = __shfl_xor_sync(0xffffffffu, bv, m);
                int   on = __shfl_xor_sync(0xffffffffu, bn, m);
                if (ov > bv || (ov == bv && on < bn)) { bv = ov; bn = on; }
            }
            if (n == 0) {
                tokSm[r] = bn;
                out[(size_t)BATCH * SEQN * NUCV + b * SEQN + s] = (float)bn;
            }
        }
        __syncthreads();

        float* t = hOld; hOld = hNew; hNew = t;
    }
}

extern "C" void kernel_launch(void* const* d_in, const int* in_sizes, int n_in,
                              void* d_out, int out_size) {
    (void)in_sizes; (void)n_in; (void)out_size;
    const float* z     = (const float*)d_in[0];
    const float* W_lh  = (const float*)d_in[1];
    const float* b_lh  = (const float*)d_in[2];
    const float* W_lc  = (const float*)d_in[3];
    const float* b_lc  = (const float*)d_in[4];
    const float* emb   = (const float*)d_in[5];
    const float* W_ih  = (const float*)d_in[6];
    const float* W_hh  = (const float*)d_in[7];
    const float* b_ih  = (const float*)d_in[8];
    const float* b_hh  = (const float*)d_in[9];
    const float* W_out = (const float*)d_in[10];
    const float* b_out = (const float*)d_in[11];
    float* out = (float*)d_out;

    // jax.random.split(key(42), 50), threefry_partitionable (foldlike)
    StepKeys keys;
    for (int s = 0; s < SEQN; s++) {
        unsigned o0, o1;
        tf2x32(0u, 42u, 0u, (unsigned)s, o0, o1);
        keys.k0[s] = o0;
        keys.k1[s] = o1;
    }

    ecomp_kernel<<<(VOCAB * GATES + 255) / 256, 256>>>(emb, W_ih);
    wpack_kernel<<<((HID + 1) * HID + 255) / 256, 256>>>(W_hh);

    cudaFuncSetAttribute(rnn_main, cudaFuncAttributeMaxDynamicSharedMemorySize, SMEM_BYTES);
    rnn_main<<<BATCH / TB, NTHREADS, SMEM_BYTES>>>(
        z, W_lh, b_lh, W_lc, b_lc, b_ih, b_hh, W_out, b_out, out, keys);
}

// round 14
// speedup vs baseline: 1.4199x; 1.0061x over previous
#include <cuda_runtime.h>
#include <cstdint>

#define BATCH   65536
#define LATENT  128
#define HID     256
#define GATES   1024
#define SEQN    50
#define NUCV    4
#define VOCAB   5
#define SOS_TOK 4

#define TB       32            // rows per CTA
#define CH       16            // rows per accumulation sweep
#define NTHREADS 256
#define PAD      36            // hT row stride: 144B = 16B-aligned for LDS.128

// SMEM layout (float offsets)
#define OFF_HA    0
#define OFF_HB    9216         // 256*PAD
#define OFF_ZS    9216         // zsm aliases hbuf1 (prologue-only use)
#define OFF_E     18432
#define OFF_WOUT  23552
#define OFF_BOUT  24576
#define OFF_TOK   24580
#define OFF_WRING 24612        // 2 slots x 2 slices x 256 float4 = 4096 floats
#define SMEM_FLOATS 28708
#define SMEM_BYTES  (SMEM_FLOATS * 4)   // 114832 B -> 2 CTAs/SM

struct StepKeys { unsigned int k0[SEQN]; unsigned int k1[SEQN]; };

__device__ float  g_E[VOCAB * GATES];        // precomputed emb[v] @ W_ih
__device__ float4 g_Wp[(HID + 1) * HID];     // repacked W_hh: [k][j] = (wi,wf,wg,wo)

// ---------------- packed f32x2 helpers (Blackwell sm_103a) ----------------
__device__ __forceinline__ unsigned long long pack2(float lo, float hi) {
    unsigned long long r;
    asm("mov.b64 %0, {%1, %2};" : "=l"(r) : "f"(lo), "f"(hi));
    return r;
}
__device__ __forceinline__ void unpack2(unsigned long long v, float& lo, float& hi) {
    asm("mov.b64 {%0, %1}, %2;" : "=f"(lo), "=f"(hi) : "l"(v));
}
__device__ __forceinline__ unsigned long long fma2(unsigned long long a,
                                                   unsigned long long b,
                                                   unsigned long long c) {
    unsigned long long d;
    asm("fma.rn.f32x2 %0, %1, %2, %3;" : "=l"(d) : "l"(a), "l"(b), "l"(c));
    return d;
}

// ---------------- cp.async helpers ----------------
__device__ __forceinline__ void cp_async16(unsigned int daddr, const void* src) {
    asm volatile("cp.async.cg.shared.global [%0], [%1], 16;\n" :: "r"(daddr), "l"(src));
}
__device__ __forceinline__ void cp_commit() {
    asm volatile("cp.async.commit_group;\n");
}
__device__ __forceinline__ void cp_wait1() {
    asm volatile("cp.async.wait_group 1;\n");
}

// ---------------- Threefry-2x32 (matches jax/_src/prng.py) ----------------
__host__ __device__ __forceinline__ unsigned int rotl32(unsigned int x, int d) {
    return (x << d) | (x >> (32 - d));
}

__host__ __device__ __forceinline__ void tf2x32(unsigned int k0, unsigned int k1,
                                                unsigned int x0, unsigned int x1,
                                                unsigned int& o0, unsigned int& o1)
{
    unsigned int k2 = k0 ^ k1 ^ 0x1BD11BDAu;
    x0 += k0; x1 += k1;
    x0 += x1; x1 = rotl32(x1, 13); x1 ^= x0;
    x0 += x1; x1 = rotl32(x1, 15); x1 ^= x0;
    x0 += x1; x1 = rotl32(x1, 26); x1 ^= x0;
    x0 += x1; x1 = rotl32(x1, 6);  x1 ^= x0;
    x0 += k1; x1 += k2 + 1u;
    x0 += x1; x1 = rotl32(x1, 17); x1 ^= x0;
    x0 += x1; x1 = rotl32(x1, 29); x1 ^= x0;
    x0 += x1; x1 = rotl32(x1, 16); x1 ^= x0;
    x0 += x1; x1 = rotl32(x1, 24); x1 ^= x0;
    x0 += k2; x1 += k0 + 2u;
    x0 += x1; x1 = rotl32(x1, 13); x1 ^= x0;
    x0 += x1; x1 = rotl32(x1, 15); x1 ^= x0;
    x0 += x1; x1 = rotl32(x1, 26); x1 ^= x0;
    x0 += x1; x1 = rotl32(x1, 6);  x1 ^= x0;
    x0 += k0; x1 += k1 + 3u;
    x0 += x1; x1 = rotl32(x1, 17); x1 ^= x0;
    x0 += x1; x1 = rotl32(x1, 29); x1 ^= x0;
    x0 += x1; x1 = rotl32(x1, 16); x1 ^= x0;
    x0 += x1; x1 = rotl32(x1, 24); x1 ^= x0;
    x0 += k1; x1 += k2 + 4u;
    x0 += x1; x1 = rotl32(x1, 13); x1 ^= x0;
    x0 += x1; x1 = rotl32(x1, 15); x1 ^= x0;
    x0 += x1; x1 = rotl32(x1, 26); x1 ^= x0;
    x0 += x1; x1 = rotl32(x1, 6);  x1 ^= x0;
    x0 += k2; x1 += k0 + 5u;
    o0 = x0; o1 = x1;
}

// ---------------- XLA-exact activations ----------------
__device__ __forceinline__ float xla_tanh(float x) {
    float ax = fabsf(x);
    float xc = fminf(fmaxf(x, -7.90531110763549805f), 7.90531110763549805f);
    float x2 = __fmul_rn(xc, xc);
    float p = -2.76076847742355e-16f;
    p = __fadd_rn(__fmul_rn(p, x2), 2.00018790482477e-13f);
    p = __fadd_rn(__fmul_rn(p, x2), -8.60467152213735e-11f);
    p = __fadd_rn(__fmul_rn(p, x2), 5.12229709037114e-08f);
    p = __fadd_rn(__fmul_rn(p, x2), 1.48572235717979e-05f);
    p = __fadd_rn(__fmul_rn(p, x2), 6.37261928875436e-04f);
    p = __fadd_rn(__fmul_rn(p, x2), 4.89352455891786e-03f);
    float num = __fmul_rn(xc, p);
    float q = 1.19825839466702e-06f;
    q = __fadd_rn(__fmul_rn(q, x2), 1.18534705686654e-04f);
    q = __fadd_rn(__fmul_rn(q, x2), 2.26843463243900e-03f);
    q = __fadd_rn(__fmul_rn(q, x2), 4.89352518554385e-03f);
    float r = __fdiv_rn(num, q);
    return (ax < 0.0004f) ? x : r;
}

__device__ __forceinline__ float xla_sigmoid(float x) {
    return __fadd_rn(0.5f, __fmul_rn(0.5f, xla_tanh(__fmul_rn(0.5f, x))));
}

// correctly-rounded f32 log via double
__device__ __forceinline__ float exact_logf(float x) {
    return (float)log((double)x);
}

// ---------------- E-table kernel: E[v][col] = emb[v] @ W_ih[:,col] ----------------
__global__ void ecomp_kernel(const float* __restrict__ emb, const float* __restrict__ W_ih) {
    int idx = blockIdx.x * blockDim.x + threadIdx.x;
    if (idx >= VOCAB * GATES) return;
    int v = idx / GATES, col = idx - v * GATES;
    float acc = 0.0f;
    for (int k = 0; k < HID; k++)
        acc = __fmaf_rn(emb[v * HID + k], W_ih[k * GATES + col], acc);
    g_E[idx] = acc;
}

// ---------------- W repack kernel: g_Wp[k][j] = (wi,wf,wg,wo) ----------------
__global__ void wpack_kernel(const float* __restrict__ W_hh) {
    int idx = blockIdx.x * blockDim.x + threadIdx.x;
    if (idx >= (HID + 1) * HID) return;
    int k = idx >> 8, j = idx & (HID - 1);
    float4 w;
    if (k < HID) {
        w.x = W_hh[(size_t)k * GATES + j];
        w.y = W_hh[(size_t)k * GATES + 256 + j];
        w.z = W_hh[(size_t)k * GATES + 512 + j];
        w.w = W_hh[(size_t)k * GATES + 768 + j];
    } else {
        w.x = w.y = w.z = w.w = 0.0f;
    }
    g_Wp[idx] = w;
}

// ---------------- Main persistent-per-CTA LSTM kernel ----------------
__global__ void __launch_bounds__(NTHREADS, 2)
rnn_main(const float* __restrict__ z,
         const float* __restrict__ W_lh, const float* __restrict__ b_lh,
         const float* __restrict__ W_lc, const float* __restrict__ b_lc,
         const float* __restrict__ b_ih, const float* __restrict__ b_hh,
         const float* __restrict__ W_out, const float* __restrict__ b_out,
         float* __restrict__ out, StepKeys keys)
{
    extern __shared__ float sm[];
    float* hbuf0   = sm + OFF_HA;      // hT[unit][row], PAD-strided
    float* hbuf1   = sm + OFF_HB;
    float* zsm     = sm + OFF_ZS;      // aliases hbuf1 (prologue only)
    float* Esm     = sm + OFF_E;       // [5][1024]
    float* WoutSm  = sm + OFF_WOUT;    // [256][4]
    float* boutSm  = sm + OFF_BOUT;    // [4]
    int*   tokSm   = (int*)(sm + OFF_TOK);  // [32]
    // W ring: 2 slots x 2 slices x 4096B; thread j owns its 16B in each slice
    const unsigned wring_u32 =
        (unsigned)__cvta_generic_to_shared(sm + OFF_WRING);

    const int tid = threadIdx.x;
    const int j   = tid;                     // hidden unit owned by this thread
    const int rowBase = blockIdx.x * TB;

    // cooperative SMEM fills
    for (int i = tid; i < VOCAB * GATES; i += NTHREADS) Esm[i] = g_E[i];
    for (int i = tid; i < HID * NUCV; i += NTHREADS)    WoutSm[i] = W_out[i];
    if (tid < NUCV) boutSm[tid] = b_out[tid];
    if (tid < TB)   tokSm[tid]  = SOS_TOK;
    for (int i = tid; i < TB * LATENT; i += NTHREADS)
        zsm[i] = z[(size_t)rowBase * LATENT + i];
    __syncthreads();

    // per-thread persistent cell state c[row] for unit j
    float creg[TB];

    // ---- prologue: h0 = tanh(z@W_lh + b_lh), c0 = tanh(z@W_lc + b_lc) ----
    {
        const float* wlh = W_lh + j;
        const float* wlc = W_lc + j;
        float blh = b_lh[j], blc = b_lc[j];
        #pragma unroll
        for (int ch = 0; ch < TB / CH; ch++) {
            float ah[CH], ac[CH];
            #pragma unroll
            for (int rr = 0; rr < CH; rr++) { ah[rr] = 0.0f; ac[rr] = 0.0f; }
            for (int k = 0; k < LATENT; k++) {
                float wh = wlh[k * HID];
                float wc = wlc[k * HID];
                #pragma unroll
                for (int rr = 0; rr < CH; rr++) {
                    float zv = zsm[(ch * CH + rr) * LATENT + k];
                    ah[rr] = __fmaf_rn(zv, wh, ah[rr]);
                    ac[rr] = __fmaf_rn(zv, wc, ac[rr]);
                }
            }
            #pragma unroll
            for (int rr = 0; rr < CH; rr++) {
                int r = ch * CH + rr;
                hbuf0[j * PAD + r] = xla_tanh(__fadd_rn(ah[rr], blh));
                creg[r]            = xla_tanh(__fadd_rn(ac[rr], blc));
            }
        }
    }
    __syncthreads();   // also orders zsm reads before hbuf1 (alias) writes

    // loop-invariant biases for this unit's 4 gate columns
    float bih0 = b_ih[j],       bih1 = b_ih[256 + j];
    float bih2 = b_ih[512 + j], bih3 = b_ih[768 + j];
    float bhh0 = b_hh[j],       bhh1 = b_hh[256 + j];
    float bhh2 = b_hh[512 + j], bhh3 = b_hh[768 + j];

    float* hOld = hbuf0;
    float* hNew = hbuf1;
    const float4* __restrict__ WpJ = g_Wp + j;     // [k][j], stride HID per k
    const unsigned myring = wring_u32 + (unsigned)(j * 16);
    const char* WringJ = (const char*)(sm + OFF_WRING) + j * 16;

    for (int s = 0; s < SEQN; s++) {
        // ---- gates: h @ W_hh via fma.rn.f32x2; W double-buffered by cp.async.
        // Block = 2 k-iterations. Slot b&1 holds block b (2 slices of 4KB).
        // Ring slots are per-thread-private (thread j only touches its 16B),
        // so wait_group is the only sync needed — no barriers.
        #pragma unroll
        for (int ch = 0; ch < TB / CH; ch++) {
            unsigned long long ai[CH/2], af_[CH/2], ag[CH/2], ao[CH/2];
            #pragma unroll
            for (int rp = 0; rp < CH/2; rp++) {
                ai[rp] = 0ULL; af_[rp] = 0ULL; ag[rp] = 0ULL; ao[rp] = 0ULL;
            }
            // stage block 0 -> slot 0, block 1 -> slot 1
            cp_async16(myring + 0,    WpJ + 0 * HID);
            cp_async16(myring + 4096, WpJ + 1 * HID);
            cp_commit();
            cp_async16(myring + 8192,  WpJ + 2 * HID);
            cp_async16(myring + 12288, WpJ + 3 * HID);
            cp_commit();

            const float* hrow = hOld + ch * CH;
            #pragma unroll 2
            for (int kb = 0; kb < HID / 2; kb++) {
                cp_wait1();                         // block kb resident
                const unsigned slot = (kb & 1) ? 8192u : 0u;
                #pragma unroll
                for (int t = 0; t < 2; t++) {
                    int k = 2 * kb + t;
                    float4 wc = *(const float4*)(WringJ + slot + t * 4096);
                    unsigned long long wi2 = pack2(wc.x, wc.x);
                    unsigned long long wf2 = pack2(wc.y, wc.y);
                    unsigned long long wg2 = pack2(wc.z, wc.z);
                    unsigned long long wo2 = pack2(wc.w, wc.w);
                    const ulonglong2* h4 = (const ulonglong2*)(hrow + k * PAD);
                    #pragma unroll
                    for (int q = 0; q < CH / 4; q++) {
                        ulonglong2 hp = h4[q];
                        ai [2*q]   = fma2(hp.x, wi2, ai [2*q]);
                        af_[2*q]   = fma2(hp.x, wf2, af_[2*q]);
                        ag [2*q]   = fma2(hp.x, wg2, ag [2*q]);
                        ao [2*q]   = fma2(hp.x, wo2, ao [2*q]);
                        ai [2*q+1] = fma2(hp.y, wi2, ai [2*q+1]);
                        af_[2*q+1] = fma2(hp.y, wf2, af_[2*q+1]);
                        ag [2*q+1] = fma2(hp.y, wg2, ag [2*q+1]);
                        ao [2*q+1] = fma2(hp.y, wo2, ao [2*q+1]);
                    }
                }
                // stage block kb+2 into the slot just consumed
                if (kb + 2 < HID / 2) {
                    cp_async16(myring + slot,        WpJ + (2 * (kb + 2))     * HID);
                    cp_async16(myring + slot + 4096, WpJ + (2 * (kb + 2) + 1) * HID);
                }
                cp_commit();   // commit every block (empty at tail keeps count aligned)
            }
            // ---- pointwise cell update; association matches ((xW+b_ih)+hW)+b_hh ----
            #pragma unroll
            for (int rp = 0; rp < CH / 2; rp++) {
                float aiL, aiH, afL, afH, agL, agH, aoL, aoH;
                unpack2(ai [rp], aiL, aiH);
                unpack2(af_[rp], afL, afH);
                unpack2(ag [rp], agL, agH);
                unpack2(ao [rp], aoL, aoH);
                #pragma unroll
                for (int lane = 0; lane < 2; lane++) {
                    int r = ch * CH + 2 * rp + lane;
                    float aI = lane ? aiH : aiL;
                    float aF = lane ? afH : afL;
                    float aG = lane ? agH : agL;
                    float aO = lane ? aoH : aoL;
                    int tok = tokSm[r];
                    const float* Ev = Esm + tok * GATES + j;
                    float gi = __fadd_rn(__fadd_rn(__fadd_rn(Ev[0],   bih0), aI), bhh0);
                    float gf = __fadd_rn(__fadd_rn(__fadd_rn(Ev[256], bih1), aF), bhh1);
                    float gg = __fadd_rn(__fadd_rn(__fadd_rn(Ev[512], bih2), aG), bhh2);
                    float go = __fadd_rn(__fadd_rn(__fadd_rn(Ev[768], bih3), aO), bhh3);
                    float iv = xla_sigmoid(gi);
                    float fv = xla_sigmoid(gf);
                    float gv = xla_tanh(gg);
                    float ov = xla_sigmoid(go);
                    float cc = __fadd_rn(__fmul_rn(fv, creg[r]), __fmul_rn(iv, gv));
                    creg[r] = cc;
                    hNew[j * PAD + r] = __fmul_rn(ov, xla_tanh(cc));
                }
            }
        }
        __syncthreads();

        // ---- merged logits + exact categorical sampling (128 threads) ----
        // Uniform whole-warp control flow; exact double log path (R12-proven).
        if (tid < TB * NUCV) {
            int r = tid >> 2, n = tid & 3;
            float acc = 0.0f;
            for (int k = 0; k < HID; k++)
                acc = __fmaf_rn(hNew[k * PAD + r], WoutSm[k * NUCV + n], acc);
            float lg = __fadd_rn(acc, boutSm[n]);
            size_t b = (size_t)(rowBase + r);
            out[(b * SEQN + s) * NUCV + n] = lg;

            unsigned o0, o1;
            tf2x32(keys.k0[s], keys.k1[s], 0u,
                   (unsigned)b * (unsigned)NUCV + (unsigned)n, o0, o1);
            unsigned bits = o0 ^ o1;
            unsigned fb = (bits >> 9) | 0x3f800000u;
            float u = __fadd_rn(__uint_as_float(fb), -1.0f);
            u = fmaxf(u, 1.17549435e-38f);              // minval = tiny
            float lu  = exact_logf(u);
            float gum = -exact_logf(-lu);
            float v = __fadd_rn(gum, lg);

            float bv = v; int bn = n;
            #pragma unroll
            for (int m = 1; m < 4; m <<= 1) {
                float ov = __shfl_xor_sync(0xffffffffu, bv, m);
                int   on = __shfl_xor_sync(0xffffffffu, bn, m);
                if (ov > bv || (ov == bv && on < bn)) { bv = ov; bn = on; }
            }
            if (n == 0) {
                tokSm[r] = bn;
                out[(size_t)BATCH * SEQN * NUCV + b * SEQN + s] = (float)bn;
            }
        }
        __syncthreads();

        float* t = hOld; hOld = hNew; hNew = t;
    }
}

extern "C" void kernel_launch(void* const* d_in, const int* in_sizes, int n_in,
                              void* d_out, int out_size) {
    (void)in_sizes; (void)n_in; (void)out_size;
    const float* z     = (const float*)d_in[0];
    const float* W_lh  = (const float*)d_in[1];
    const float* b_lh  = (const float*)d_in[2];
    const float* W_lc  = (const float*)d_in[3];
    const float* b_lc  = (const float*)d_in[4];
    const float* emb   = (const float*)d_in[5];
    const float* W_ih  = (const float*)d_in[6];
    const float* W_hh  = (const float*)d_in[7];
    const float* b_ih  = (const float*)d_in[8];
    const float* b_hh  = (const float*)d_in[9];
    const float* W_out = (const float*)d_in[10];
    const float* b_out = (const float*)d_in[11];
    float* out = (float*)d_out;

    // jax.random.split(key(42), 50), threefry_partitionable (foldlike)
    StepKeys keys;
    for (int s = 0; s < SEQN; s++) {
        unsigned o0, o1;
        tf2x32(0u, 42u, 0u, (unsigned)s, o0, o1);
        keys.k0[s] = o0;
        keys.k1[s] = o1;
    }

    ecomp_kernel<<<(VOCAB * GATES + 255) / 256, 256>>>(emb, W_ih);
    wpack_kernel<<<((HID + 1) * HID + 255) / 256, 256>>>(W_hh);

    cudaFuncSetAttribute(rnn_main, cudaFuncAttributeMaxDynamicSharedMemorySize, SMEM_BYTES);
    rnn_main<<<BATCH / TB, NTHREADS, SMEM_BYTES>>>(
        z, W_lh, b_lh, W_lc, b_lc, b_ih, b_hh, W_out, b_out, out, keys);
}